// round 5
// baseline (speedup 1.0000x reference)
#include <cuda_runtime.h>
#include <cstdint>
#include <cstddef>

#define N_NODES   25
#define K_TOT     384
#define OUT_F     256
#define M_TOT     (8192 * 25)
#define NEG_BIG   (-9e15f)
#define MAXNB     24
#define NCH       12

// ---- shared memory layout (all tiles 128B-row swizzled) ----
#define OFF_X   0          // [2][128 rows][32 f]          32 KB
#define OFF_A0  32768      // [2][128][16 f2] swizzled     32 KB
#define OFF_AZ  65536      //                              32 KB
#define OFF_B   98304      // [2][512 n][16 f2] swizzled  128 KB
#define OFF_MT  229376
#define MT_DIAG 0          // 25 f
#define MT_NNZ  128        // 25 i
#define MT_PK   256        // 600 u32 (coef bits | src)
#define DSMEM   232064

__device__ float    g_WTp[2 * OUT_F * K_TOT];   // [half][n][paired pos], rna
__device__ float    g_diag[N_NODES];
__device__ int      g_nnzc[N_NODES];
__device__ uint32_t g_pk[N_NODES * MAXNB];      // (coef & ~31) | src

// ---------------- helpers ----------------
__device__ __forceinline__ float rna_tf32(float x) {
    uint32_t u; asm("cvt.rna.tf32.f32 %0, %1;" : "=r"(u) : "f"(x));
    return __uint_as_float(u);
}
__device__ __forceinline__ void cpa16(void* dst, const float* src) {
    uint32_t d = (uint32_t)__cvta_generic_to_shared(dst);
    asm volatile("cp.async.cg.shared.global [%0], [%1], 16;" :: "r"(d), "l"(src));
}
__device__ __forceinline__ void mma8(float c[4], float2 alo, float2 ahi, float2 b) {
    asm volatile(
        "mma.sync.aligned.m16n8k8.row.col.f32.tf32.tf32.f32 "
        "{%0,%1,%2,%3}, {%4,%5,%6,%7}, {%8,%9}, {%0,%1,%2,%3};\n"
        : "+f"(c[0]), "+f"(c[1]), "+f"(c[2]), "+f"(c[3])
        : "r"(__float_as_uint(alo.x)), "r"(__float_as_uint(ahi.x)),
          "r"(__float_as_uint(alo.y)), "r"(__float_as_uint(ahi.y)),
          "r"(__float_as_uint(b.x)),  "r"(__float_as_uint(b.y)));
}
#define COMMIT() asm volatile("cp.async.commit_group;")
#define WAITG1() asm volatile("cp.async.wait_group 1;")
#define WAITG0() asm volatile("cp.async.wait_group 0;")

// ================= setup ==================================================
__global__ void setup_kernel(const float* __restrict__ W,
                             const float* __restrict__ e,
                             const int*   __restrict__ rows,
                             const int*   __restrict__ cols,
                             int nnz) {
    // W^T, k-paired for f2 frag loads: pos = ch*32 + g*8 + lc*2 + h4
    // holds rna(W[h][k][n]) with k = ch*32 + g*8 + h4*4 + lc
    const int total = 2 * OUT_F * K_TOT;
    for (int i = blockIdx.x * blockDim.x + threadIdx.x; i < total;
         i += gridDim.x * blockDim.x) {
        int h   = i / (OUT_F * K_TOT);
        int rem = i - h * (OUT_F * K_TOT);
        int n   = rem / K_TOT;
        int pos = rem - n * K_TOT;
        int ch = pos >> 5, r5 = pos & 31;
        int g = r5 >> 3, q = r5 & 7;
        int lc = q >> 1, h4 = q & 1;
        int k = ch * 32 + g * 8 + h4 * 4 + lc;
        g_WTp[i] = rna_tf32(W[h * (K_TOT * OUT_F) + k * OUT_F + n]);
    }
    if (blockIdx.x == 0) {
        __shared__ float lg[N_NODES * N_NODES];
        int t = threadIdx.x;
        for (int i = t; i < N_NODES * N_NODES; i += blockDim.x) lg[i] = NEG_BIG;
        __syncthreads();
        for (int i = t; i < nnz; i += blockDim.x) lg[rows[i] * N_NODES + cols[i]] = e[i];
        __syncthreads();
        if (t < N_NODES) {
            float mx = -1e30f;
            #pragma unroll
            for (int n = 0; n < N_NODES; n++) mx = fmaxf(mx, lg[t * N_NODES + n]);
            float ex[N_NODES]; float s = 0.f;
            #pragma unroll
            for (int n = 0; n < N_NODES; n++) {
                ex[n] = expf(lg[t * N_NODES + n] - mx); s += ex[n];
            }
            float inv = 1.f / s;
            int cnt = 0;
            for (int n = 0; n < N_NODES; n++) {
                float a = ex[n] * inv;
                if (n == t) g_diag[t] = a;
                else if (lg[t * N_NODES + n] != NEG_BIG) {
                    g_pk[t * MAXNB + cnt] =
                        (__float_as_uint(a) & 0xFFFFFFE0u) | (uint32_t)n;
                    cnt++;
                }
            }
            g_nnzc[t] = cnt;
        }
    }
}

// ================= fused premix + tf32 GEMM ===============================
__global__ void __launch_bounds__(256, 1)
fused_kernel(const float* __restrict__ nodev, const float* __restrict__ hid,
             const float* __restrict__ bias, float* __restrict__ out) {
    extern __shared__ char sm[];
    const int tid = threadIdx.x, wid = tid >> 5, lid = tid & 31;
    const int lr = lid >> 2, lc = lid & 3;
    const int wm = wid >> 2, wn = wid & 3;
    const int row0  = blockIdx.x * 125;
    const int nrows = (M_TOT - row0 < 125) ? (M_TOT - row0) : 125;
    const int nbat  = nrows / 25;

    float*    s_diag = (float*)(sm + OFF_MT + MT_DIAG);
    int*      s_nnz  = (int*)  (sm + OFF_MT + MT_NNZ);
    uint32_t* s_pk   = (uint32_t*)(sm + OFF_MT + MT_PK);

    if (tid < N_NODES) { s_diag[tid] = g_diag[tid]; s_nnz[tid] = g_nnzc[tid]; }
    for (int i = tid; i < N_NODES * MAXNB; i += 256) s_pk[i] = g_pk[i];

    // ---- loaders ----
    auto fillX = [&](int s, int xb) {
        const int k0 = s * 32;
        #pragma unroll
        for (int i = 0; i < 4; i++) {
            int idx = i * 256 + tid;
            int row = idx >> 3, g = idx & 7;
            int grow = row0 + row; if (grow >= M_TOT) grow = M_TOT - 1;
            const float* src = (k0 < 128)
                ? (nodev + (size_t)grow * 128 + k0 + g * 4)
                : (hid   + (size_t)grow * 256 + (k0 - 128) + g * 4);
            cpa16(sm + OFF_X + xb * 16384 + row * 128 + g * 16, src);
        }
    };
    auto fillB = [&](int s, int bb) {
        #pragma unroll
        for (int i = 0; i < 16; i++) {
            int idx = i * 256 + tid;
            int n = idx >> 3, g = idx & 7;
            int h = n >> 8, nn = n & 255;
            cpa16(sm + OFF_B + bb * 65536 + n * 128 + ((g ^ (n & 7)) << 4),
                  g_WTp + (size_t)h * (OUT_F * K_TOT) + (size_t)nn * K_TOT
                        + s * 32 + g * 4);
        }
    };

    // premix: chunk sIdx from X[sIdx&1] -> A0/AZ[sIdx&1]
    const int pm_ks = lid >> 3, pm_r3 = lid & 7;
    const int pm_p  = pm_ks * 4 + (pm_r3 & 3);
    const int pm_h4 = pm_r3 >> 2;
    auto premix = [&](int sIdx) {
        const int buf = sIdx & 1;
        const float* X = (const float*)(sm + OFF_X + buf * 16384);
        char* A0 = sm + OFF_A0 + buf * 16384;
        char* AZ = sm + OFF_AZ + buf * 16384;
        #pragma unroll 2
        for (int r = 0; r < 16; r++) {
            int m = wid * 16 + r;
            int bl = (m * 1311) >> 15;
            if (bl > nbat - 1) bl = nbat - 1;
            int node = m - bl * 25; if (node > 24) node = 24;
            float x = X[m * 32 + lid];
            float a0 = s_diag[node] * x;
            float z = 0.f;
            int nn = s_nnz[node];
            const uint32_t* pk = s_pk + node * MAXNB;
            const float* Xb = X + (bl * 25) * 32 + lid;
            #pragma unroll 4
            for (int j = 0; j < nn; j++) {
                uint32_t u = pk[j];
                z += __uint_as_float(u & 0xFFFFFFE0u) * Xb[(u & 31u) * 32];
            }
            uint32_t off = (uint32_t)(m * 128)
                         + ((uint32_t)((pm_p >> 1) ^ (m & 7)) << 4)
                         + (pm_p & 1) * 8 + pm_h4 * 4;
            *(float*)(A0 + off) = rna_tf32(a0);
            *(float*)(AZ + off) = rna_tf32(z);
        }
    };

    // ---- prologue ----
    fillX(0, 0); fillB(0, 0); COMMIT();
    fillX(1, 1); fillB(1, 1); COMMIT();
    WAITG1(); __syncthreads();          // {X0,B0} visible
    premix(0);
    __syncthreads();                    // A(0) ready, X[0] free
    fillX(2, 0); COMMIT();              // {X2}

    float acc[4][8][4];
    #pragma unroll
    for (int a = 0; a < 4; a++)
        #pragma unroll
        for (int b = 0; b < 8; b++)
            #pragma unroll
            for (int c = 0; c < 4; c++) acc[a][b][c] = 0.f;

    const int c1 = lc >> 1, c2 = (lc & 1) * 8;

    // ---- main loop ----
    #pragma unroll 1
    for (int s = 0; s < NCH; s++) {
        const int buf = s & 1;
        WAITG1();                       // {X(s+1), B(s)} landed (own warp)
        __syncthreads();                // visible to all; prev MMA/premix done

        const char* Bbase = sm + OFF_B + buf * 65536;

        // pass 0: A0 @ W0
        {
            const char* Ab = sm + OFF_A0 + buf * 16384;
            #pragma unroll
            for (int ks = 0; ks < 4; ks++) {
                float2 alo[4], ahi[4];
                #pragma unroll
                for (int mf = 0; mf < 4; mf++) {
                    int r0 = wm * 64 + mf * 16 + lr;
                    uint32_t go = (uint32_t)(((2 * ks + c1) ^ lr) << 4) + c2;
                    alo[mf] = *(const float2*)(Ab + r0 * 128 + go);
                    ahi[mf] = *(const float2*)(Ab + (r0 + 8) * 128 + go);
                }
                #pragma unroll
                for (int nf = 0; nf < 8; nf++) {
                    int n = wn * 64 + nf * 8 + lr;
                    float2 b = *(const float2*)(Bbase + n * 128 +
                               (uint32_t)(((2 * ks + c1) ^ (n & 7)) << 4) + c2);
                    #pragma unroll
                    for (int mf = 0; mf < 4; mf++) mma8(acc[mf][nf], alo[mf], ahi[mf], b);
                }
            }
        }

        // overlap: build A(s+1) while tensor pipe drains pass-0 work
        if (s + 1 < NCH) premix(s + 1);

        // pass 1: AZ @ W1
        {
            const char* Ab = sm + OFF_AZ + buf * 16384;
            #pragma unroll
            for (int ks = 0; ks < 4; ks++) {
                float2 alo[4], ahi[4];
                #pragma unroll
                for (int mf = 0; mf < 4; mf++) {
                    int r0 = wm * 64 + mf * 16 + lr;
                    uint32_t go = (uint32_t)(((2 * ks + c1) ^ lr) << 4) + c2;
                    alo[mf] = *(const float2*)(Ab + r0 * 128 + go);
                    ahi[mf] = *(const float2*)(Ab + (r0 + 8) * 128 + go);
                }
                #pragma unroll
                for (int nf = 0; nf < 8; nf++) {
                    int n = 256 + wn * 64 + nf * 8 + lr;
                    float2 b = *(const float2*)(Bbase + n * 128 +
                               (uint32_t)(((2 * ks + c1) ^ (n & 7)) << 4) + c2);
                    #pragma unroll
                    for (int mf = 0; mf < 4; mf++) mma8(acc[mf][nf], alo[mf], ahi[mf], b);
                }
            }
        }

        __syncthreads();                // all reads of X(s+1)/A(s)/B(s) done
        if (s + 3 < NCH) fillX(s + 3, (s + 3) & 1);
        if (s + 2 < NCH) fillB(s + 2, buf);
        COMMIT();                       // (possibly empty) keeps group count uniform
    }

    // ---- epilogue: acc + bias -> out ----
    #pragma unroll
    for (int mf = 0; mf < 4; mf++) {
        const int m0 = wm * 64 + mf * 16 + lr;
        const bool v0 = m0 < nrows, v1 = (m0 + 8) < nrows;
        float* o0 = out + ((size_t)row0 + m0) * OUT_F;
        float* o1 = out + ((size_t)row0 + m0 + 8) * OUT_F;
        #pragma unroll
        for (int nf = 0; nf < 8; nf++) {
            const int c = wn * 64 + nf * 8 + lc * 2;
            float2 bv = __ldg((const float2*)(bias + c));
            if (v0) *(float2*)(o0 + c) =
                make_float2(acc[mf][nf][0] + bv.x, acc[mf][nf][1] + bv.y);
            if (v1) *(float2*)(o1 + c) =
                make_float2(acc[mf][nf][2] + bv.x, acc[mf][nf][3] + bv.y);
        }
    }
}

// ================= launcher ==============================================
extern "C" void kernel_launch(void* const* d_in, const int* in_sizes, int n_in,
                              void* d_out, int out_size) {
    const float* nodev = (const float*)d_in[0];
    const float* hid   = (const float*)d_in[1];
    const float* W     = (const float*)d_in[2];
    const float* e     = (const float*)d_in[3];
    const float* bias  = (const float*)d_in[4];
    const int*   rows  = (const int*)d_in[5];
    const int*   cols  = (const int*)d_in[6];
    const int nnz = in_sizes[3];

    setup_kernel<<<64, 256>>>(W, e, rows, cols, nnz);

    cudaFuncSetAttribute(fused_kernel,
                         cudaFuncAttributeMaxDynamicSharedMemorySize, DSMEM);
    const int grid = (M_TOT + 124) / 125;   // 1639
    fused_kernel<<<grid, 256, DSMEM>>>(nodev, hid, bias, (float*)d_out);
    (void)n_in; (void)out_size;
}